// round 8
// baseline (speedup 1.0000x reference)
#include <cuda_runtime.h>
#include <cstdint>

// Problem constants:
//   B=8, H=8, L=1024, D=64, K=49
//   x:  (B,H,L,D) fp32   = d_in[0]
//   W:  (H,D,K)   fp32   = d_in[1]
//   rp: (L,L)     int32  = d_in[2]
//   out:(B,H,L,L) fp32
#define BB 8
#define HH 8
#define LL 1024
#define DD 64
#define KK 49
#define BH (BB*HH)

#define WS_STRIDE 50       // padded W row stride (even -> aligned pairs)
#define WPB 8              // warps per block
#define NPH 2              // i-phases per warp -> 16 i per block

// ---------------------------------------------------------------------------
// Fused kernel v5: FFMA2 compute + warp-local smem gather, single-wave grid.
//
// Block (i-group, h): 8 warps; warp w handles i = i0 + ph*8 + w for ph=0,1,
// and ALL 8 b's for that i.
//   compute: acc[bp]   = { lt[2bp][lane],   lt[2bp+1][lane]   }
//            acc[4+bp] = { lt[2bp][lane+32], lt[2bp+1][lane+32] } (lanes 0..16)
//            x pairs via broadcast LDS.128 from transposed stage.
//   gather:  spill lt -> lts[w] (warp-local), then per quad 4 LDS.32
//            (<=2-way bank conflict: only k and k+32 collide) + STG.128.
// grid: (L/16, H) = (64, 8) = 512 blocks, 256 thr -> 5 blocks/SM, ONE wave.
// ---------------------------------------------------------------------------
__global__ __launch_bounds__(256, 5) void irpe_fused5_kernel(
    const float* __restrict__ x, const float* __restrict__ W,
    const int* __restrict__ rp, float* __restrict__ out)
{
    const int h    = blockIdx.y;
    const int i0   = blockIdx.x * (WPB * NPH);
    const int tid  = threadIdx.x;
    const int w    = tid >> 5;
    const int lane = tid & 31;

    __shared__ float Ws[DD * WS_STRIDE + 32];     // ~13 KB
    __shared__ float xst[WPB * DD * BB];          // [w][d][b], 16 KB (reused per phase)
    __shared__ float lts[WPB * BB * KK];          // [w][b][k], 12.25 KB (warp-local)

    // Stage W[h] into stride-50 rows (once)
    {
        const float* Wh = W + (size_t)h * DD * KK;
        #pragma unroll
        for (int t = tid; t < DD * KK; t += 256) {
            const int d = t / KK;
            const int k = t - d * KK;
            Ws[d * WS_STRIDE + k] = Wh[t];
        }
    }

    for (int ph = 0; ph < NPH; ph++) {
        const int ibase = i0 + ph * WPB;
        const int i     = ibase + w;

        // Barrier: Ws ready (ph0) / all warps done reading xst of prev phase.
        __syncthreads();

        // Stage x transposed: xst[ww][d][b] = x[b*8+h][ibase+ww][d]
        #pragma unroll
        for (int t = tid; t < WPB * BB * (DD / 4); t += 256) {
            const int ww  = t >> 7;
            const int rem = t & 127;
            const int b   = rem >> 4;
            const int q   = rem & 15;
            float4 v = *(const float4*)(x + ((size_t)(b * HH + h) * LL + ibase + ww) * DD + q * 4);
            float* dst = xst + (ww * DD + q * 4) * BB + b;
            dst[0 * BB] = v.x;
            dst[1 * BB] = v.y;
            dst[2 * BB] = v.z;
            dst[3 * BB] = v.w;
        }
        __syncthreads();

        // Compute lt for all 8 b (b-pairs packed in f32x2)
        unsigned long long acc[8];
        #pragma unroll
        for (int j = 0; j < 8; j++) acc[j] = 0ull;

        const ulonglong2* xw = (const ulonglong2*)(xst + w * DD * BB);

        #pragma unroll 16
        for (int d = 0; d < DD; d++) {
            const float w0 = Ws[d * WS_STRIDE + lane];
            const float w1 = Ws[d * WS_STRIDE + 32 + lane];  // junk lanes>=17, discarded
            unsigned long long wp0, wp1;
            asm("mov.b64 %0, {%1, %1};" : "=l"(wp0) : "f"(w0));
            asm("mov.b64 %0, {%1, %1};" : "=l"(wp1) : "f"(w1));
            const ulonglong2 xq0 = xw[d * 2];       // {b0b1, b2b3} broadcast LDS.128
            const ulonglong2 xq1 = xw[d * 2 + 1];   // {b4b5, b6b7}
            asm("fma.rn.f32x2 %0, %1, %2, %0;" : "+l"(acc[0]) : "l"(xq0.x), "l"(wp0));
            asm("fma.rn.f32x2 %0, %1, %2, %0;" : "+l"(acc[1]) : "l"(xq0.y), "l"(wp0));
            asm("fma.rn.f32x2 %0, %1, %2, %0;" : "+l"(acc[2]) : "l"(xq1.x), "l"(wp0));
            asm("fma.rn.f32x2 %0, %1, %2, %0;" : "+l"(acc[3]) : "l"(xq1.y), "l"(wp0));
            asm("fma.rn.f32x2 %0, %1, %2, %0;" : "+l"(acc[4]) : "l"(xq0.x), "l"(wp1));
            asm("fma.rn.f32x2 %0, %1, %2, %0;" : "+l"(acc[5]) : "l"(xq0.y), "l"(wp1));
            asm("fma.rn.f32x2 %0, %1, %2, %0;" : "+l"(acc[6]) : "l"(xq1.x), "l"(wp1));
            asm("fma.rn.f32x2 %0, %1, %2, %0;" : "+l"(acc[7]) : "l"(xq1.y), "l"(wp1));
        }

        // Spill lt to warp-local smem region
        float* lw = lts + w * (BB * KK);
        #pragma unroll
        for (int bp = 0; bp < 4; bp++) {
            float lo, hi;
            asm("mov.b64 {%0, %1}, %2;" : "=f"(lo), "=f"(hi) : "l"(acc[bp]));
            lw[(2 * bp)     * KK + lane] = lo;
            lw[(2 * bp + 1) * KK + lane] = hi;
            if (lane < KK - 32) {
                asm("mov.b64 {%0, %1}, %2;" : "=f"(lo), "=f"(hi) : "l"(acc[4 + bp]));
                lw[(2 * bp)     * KK + 32 + lane] = lo;
                lw[(2 * bp + 1) * KK + 32 + lane] = hi;
            }
        }
        __syncwarp();

        // Gather + streaming stores
        const int4* rrow = (const int4*)(rp + (size_t)i * LL);
        #pragma unroll 2
        for (int it = 0; it < 8; it++) {
            const int4 bk = rrow[it * 32 + lane];   // coalesced LDG.128
            #pragma unroll
            for (int b = 0; b < BB; b++) {
                const float* row = lw + b * KK;
                float4 v;
                v.x = row[bk.x];
                v.y = row[bk.y];
                v.z = row[bk.z];
                v.w = row[bk.w];
                float4* dst = (float4*)(out + (((size_t)(b * HH + h)) * LL + i) * LL);
                __stcs(dst + it * 32 + lane, v);
            }
        }
    }
}

// ---------------------------------------------------------------------------
extern "C" void kernel_launch(void* const* d_in, const int* in_sizes, int n_in,
                              void* d_out, int out_size)
{
    const float* x  = (const float*)d_in[0];
    const float* W  = (const float*)d_in[1];
    const int*   rp = (const int*)d_in[2];
    float*       out = (float*)d_out;

    dim3 grid(LL / (WPB * NPH), HH);
    irpe_fused5_kernel<<<grid, 256>>>(x, W, rp, out);
}

// round 9
// speedup vs baseline: 1.2428x; 1.2428x over previous
#include <cuda_runtime.h>
#include <cstdint>

// Problem constants:
//   B=8, H=8, L=1024, D=64, K=49
//   x:  (B,H,L,D) fp32   = d_in[0]
//   W:  (H,D,K)   fp32   = d_in[1]
//   rp: (L,L)     int32  = d_in[2]
//   out:(B,H,L,L) fp32
// Structure: i = row_i*32 + col_i, j = rj*32 + cj,
//   rp[i][j] = (pw(row_i-rj)+3)*7 + (pw(col_i-cj)+3), pw in [-3,3].
#define BB 8
#define HH 8
#define LL 1024
#define DD 64
#define KK 49
#define BH (BB*HH)

#define WS_STRIDE 50       // padded W row stride (even -> aligned pairs)
#define IPB 8              // i-rows per block (one per warp)

// ---------------------------------------------------------------------------
// Fused kernel v6: FFMA2 compute + separable-index gather.
//   Per warp (owns i, all 8 b):
//     cidx[lane] and rbase[lane(=rj)] extracted from two rp loads;
//     bucket(rj, lane) = rbase[rj] + cidx[lane]  (no per-element rp reads).
//   Gather: spill lt once to warp-local smem, then per rj: 1 shfl + per b:
//     1 broadcast LDS.32 (<=7 distinct words/banks -> conflict-free) + STG.32.
// grid: (L/8, H) = (128, 8), block: 256.
// ---------------------------------------------------------------------------
__global__ __launch_bounds__(256, 5) void irpe_fused6_kernel(
    const float* __restrict__ x, const float* __restrict__ W,
    const int* __restrict__ rp, float* __restrict__ out)
{
    const int h    = blockIdx.y;
    const int i0   = blockIdx.x * IPB;
    const int tid  = threadIdx.x;
    const int w    = tid >> 5;
    const int lane = tid & 31;
    const int i    = i0 + w;
    const int row_i = i >> 5;
    const int col_i = i & 31;

    __shared__ float Ws[DD * WS_STRIDE + 32];     // ~13 KB
    __shared__ float xst[IPB * DD * BB];          // [w][d][b], 16 KB
    __shared__ float lts[IPB * BB * KK];          // [w][b][k], 12.25 KB

    // Index extraction (two tiny rp reads per warp)
    const int cidx  = rp[(size_t)i * LL + row_i * 32 + lane] - 21;  // coalesced
    const int rbase = rp[(size_t)i * LL + lane * 32 + col_i] - 3;   // lane = rj

    // Stage W[h] into stride-50 rows
    {
        const float* Wh = W + (size_t)h * DD * KK;
        #pragma unroll
        for (int t = tid; t < DD * KK; t += 256) {
            const int d = t / KK;
            const int k = t - d * KK;
            Ws[d * WS_STRIDE + k] = Wh[t];
        }
    }

    // Stage x transposed: xst[ww][d][b] = x[b*8+h][i0+ww][d]
    #pragma unroll
    for (int t = tid; t < IPB * BB * (DD / 4); t += 256) {
        const int ww  = t >> 7;
        const int rem = t & 127;
        const int b   = rem >> 4;
        const int q   = rem & 15;
        float4 v = *(const float4*)(x + ((size_t)(b * HH + h) * LL + i0 + ww) * DD + q * 4);
        float* dst = xst + (ww * DD + q * 4) * BB + b;
        dst[0 * BB] = v.x;
        dst[1 * BB] = v.y;
        dst[2 * BB] = v.z;
        dst[3 * BB] = v.w;
    }
    __syncthreads();

    // Compute lt for all 8 b (b-pairs packed in f32x2)
    unsigned long long acc[8];
    #pragma unroll
    for (int j = 0; j < 8; j++) acc[j] = 0ull;

    const ulonglong2* xw = (const ulonglong2*)(xst + w * DD * BB);

    #pragma unroll 16
    for (int d = 0; d < DD; d++) {
        const float w0 = Ws[d * WS_STRIDE + lane];
        const float w1 = Ws[d * WS_STRIDE + 32 + lane];  // junk lanes>=17, discarded
        unsigned long long wp0, wp1;
        asm("mov.b64 %0, {%1, %1};" : "=l"(wp0) : "f"(w0));
        asm("mov.b64 %0, {%1, %1};" : "=l"(wp1) : "f"(w1));
        const ulonglong2 xq0 = xw[d * 2];       // broadcast LDS.128
        const ulonglong2 xq1 = xw[d * 2 + 1];
        asm("fma.rn.f32x2 %0, %1, %2, %0;" : "+l"(acc[0]) : "l"(xq0.x), "l"(wp0));
        asm("fma.rn.f32x2 %0, %1, %2, %0;" : "+l"(acc[1]) : "l"(xq0.y), "l"(wp0));
        asm("fma.rn.f32x2 %0, %1, %2, %0;" : "+l"(acc[2]) : "l"(xq1.x), "l"(wp0));
        asm("fma.rn.f32x2 %0, %1, %2, %0;" : "+l"(acc[3]) : "l"(xq1.y), "l"(wp0));
        asm("fma.rn.f32x2 %0, %1, %2, %0;" : "+l"(acc[4]) : "l"(xq0.x), "l"(wp1));
        asm("fma.rn.f32x2 %0, %1, %2, %0;" : "+l"(acc[5]) : "l"(xq0.y), "l"(wp1));
        asm("fma.rn.f32x2 %0, %1, %2, %0;" : "+l"(acc[6]) : "l"(xq1.x), "l"(wp1));
        asm("fma.rn.f32x2 %0, %1, %2, %0;" : "+l"(acc[7]) : "l"(xq1.y), "l"(wp1));
    }

    // Spill lt to warp-local smem region: lw[b*49 + k]
    float* lw = lts + w * (BB * KK);
    #pragma unroll
    for (int bp = 0; bp < 4; bp++) {
        float lo, hi;
        asm("mov.b64 {%0, %1}, %2;" : "=f"(lo), "=f"(hi) : "l"(acc[bp]));
        lw[(2 * bp)     * KK + lane] = lo;
        lw[(2 * bp + 1) * KK + lane] = hi;
        if (lane < KK - 32) {
            asm("mov.b64 {%0, %1}, %2;" : "=f"(lo), "=f"(hi) : "l"(acc[4 + bp]));
            lw[(2 * bp)     * KK + 32 + lane] = lo;
            lw[(2 * bp + 1) * KK + 32 + lane] = hi;
        }
    }
    __syncwarp();

    // Gather + streaming stores.
    // out[b*8+h][i][rj*32+lane] = lw[b*49 + rbase(rj) + cidx(lane)]
    const float* lwc = lw + cidx;
    float* ob = out + ((size_t)h * LL + i) * LL + lane;   // b=0 base
    #pragma unroll 4
    for (int rj = 0; rj < 32; rj++) {
        const int rb = __shfl_sync(0xffffffffu, rbase, rj);
        const float* src = lwc + rb;
        float* dst = ob + rj * 32;
        #pragma unroll
        for (int b = 0; b < BB; b++) {
            const float v = src[b * KK];                       // broadcast LDS
            __stcs(dst + (size_t)b * (HH * LL * LL), v);       // coalesced STG.32
        }
    }
}

// ---------------------------------------------------------------------------
extern "C" void kernel_launch(void* const* d_in, const int* in_sizes, int n_in,
                              void* d_out, int out_size)
{
    const float* x  = (const float*)d_in[0];
    const float* W  = (const float*)d_in[1];
    const int*   rp = (const int*)d_in[2];
    float*       out = (float*)d_out;

    dim3 grid(LL / IPB, HH);
    irpe_fused6_kernel<<<grid, 256>>>(x, W, rp, out);
}